// round 5
// baseline (speedup 1.0000x reference)
#include <cuda_runtime.h>
#include <cstdint>

#define N        1024
#define LOGN     10
#define NN       (1<<20)
#define NZ       24
#define PAIRS    12
#define ROI2     512
#define LO       256
#define EXT      64
#define INNER    896
#define SNRV     200.0f
#define BKG      110.0f
#define ITN      2
#define KSEL0    524287u
#define KSEL1    524288u

#define ROWS     4
#define STRIDE   1032          /* float2 row pitch in shared (pad vs bank conflicts) */
#define TPB      128

// ---------------- static device scratch (no runtime allocation allowed) ----------------
__device__ float2   g_W [(size_t)PAIRS * NN];   // 96 MB ping
__device__ float2   g_W2[(size_t)PAIRS * NN];   // 96 MB pong
__device__ float2   g_Khb[NN];                  // Hermitian kernel spectrum, bitrev layout
__device__ float    g_ImgExp[NN];
__device__ float    g_ImgEst[NN];
__device__ float2   g_tw[N/2];
__device__ double   g_ksum;
__device__ float    g_scale;                    // 1/(N^2 * Ksum)
__device__ unsigned g_hist[65536];
__device__ unsigned g_sel[4];                   // bin0, rem0, bin1, rem1
__device__ unsigned g_val[2];
__device__ float    g_medScale;                 // median / SNR

__device__ __forceinline__ float2 cmul(float2 a, float2 b){
    return make_float2(a.x*b.x - a.y*b.y, a.x*b.y + a.y*b.x);
}

// ---------------- setup kernels ----------------
__global__ void k_zero_scalars(){ g_ksum = 0.0; }

__global__ void k_tw(){
    int k = blockIdx.x*blockDim.x + threadIdx.x;
    if (k < N/2){
        double a = -6.283185307179586 * (double)k / (double)N;
        g_tw[k] = make_float2((float)cos(a), (float)sin(a));
    }
}

__global__ void k_imgexp(const float* __restrict__ img){
    int i = blockIdx.x*blockDim.x + threadIdx.x;
    if (i >= NN) return;
    int y = i >> LOGN, x = i & (N-1);
    float v = 0.f;
    if (y >= EXT && y < N-EXT && x >= EXT && x < N-EXT){
        float t = img[(y-EXT)*INNER + (x-EXT)] - BKG;
        v = t > 0.f ? t : 0.f;
    }
    g_ImgExp[i] = v;
}

__global__ void k_ksum(const float* __restrict__ cr){
    __shared__ float s[256];
    float acc = 0.f;
    for (int i = blockIdx.x*blockDim.x + threadIdx.x; i < NN; i += gridDim.x*blockDim.x)
        acc += cr[i];
    s[threadIdx.x] = acc; __syncthreads();
    for (int o = 128; o > 0; o >>= 1){
        if (threadIdx.x < o) s[threadIdx.x] += s[threadIdx.x+o];
        __syncthreads();
    }
    if (threadIdx.x == 0) atomicAdd(&g_ksum, (double)s[0]);
}

__global__ void k_scale_final(){
    g_scale = (float)(1.0 / (1048576.0 * g_ksum));
}

// Kh(f) = (K(f)+conj(K(-f)))/2, stored at bit-reversed (y,x) so the DIF/DIF
// scrambled spectrum can be multiplied with natural storage indices.
__global__ void k_kh(const float* __restrict__ cr, const float* __restrict__ ci){
    int i = blockIdx.x*blockDim.x + threadIdx.x;
    if (i >= NN) return;
    int y = i >> LOGN, x = i & (N-1);
    int ny = (N - y) & (N-1), nx = (N - x) & (N-1);
    float kr = cr[i], ki = ci[i];
    float mr = cr[ny*N + nx], mi = ci[ny*N + nx];
    float2 kh = make_float2(0.5f*(kr + mr), 0.5f*(ki - mi));
    int ry = __brev(y) >> (32-LOGN), rx = __brev(x) >> (32-LOGN);
    g_Khb[ry*N + rx] = kh;
}

// ---------------- fused 1D-FFT + transpose pass ----------------
// forward: DIF (natural in -> bitrev out at natural storage index)
// inverse: DIT (bitrev in -> natural out). No reversal permutes needed.
enum { IN_PLANE=0, IN_PAIRS=1, IN_SPECMUL=2, IN_SPECMUL_CONJ=3, IN_RATIO=4 };

__global__ void k_fft(const float2* __restrict__ src, float2* __restrict__ dst,
                      int mode, int inverse, const float* __restrict__ obj)
{
    __shared__ float2 sh[ROWS*STRIDE + N/2];
    float2* rows = sh;
    float2* tw   = sh + ROWS*STRIDE;

    int tid  = threadIdx.x;
    int p    = blockIdx.y;
    int row0 = blockIdx.x * ROWS;
    size_t poff = (size_t)p * NN;

    for (int k = tid; k < N/2; k += TPB) tw[k] = g_tw[k];

    // coalesced load of ROWS rows, with fused input construction
    for (int e = tid; e < ROWS*N; e += TPB){
        int rr = e >> LOGN;
        int x  = e & (N-1);
        int y  = row0 + rr;
        float2 v;
        if (mode == IN_PLANE){
            v = src[poff + (size_t)y*N + x];
        } else if (mode == IN_PAIRS){
            v = make_float2(0.f, 0.f);
            if (y >= LO && y < LO+ROI2 && x >= LO && x < LO+ROI2){
                int r = (y-LO)*ROI2 + (x-LO);
                v.x = obj[(size_t)(2*p  )*ROI2*ROI2 + r];
                v.y = obj[(size_t)(2*p+1)*ROI2*ROI2 + r];
            }
        } else if (mode == IN_SPECMUL || mode == IN_SPECMUL_CONJ){
            float2 a = src[poff + (size_t)y*N + x];
            float2 k = g_Khb[y*N + x];
            if (mode == IN_SPECMUL_CONJ) k.y = -k.y;
            float s = g_scale;
            v = cmul(a, k); v.x *= s; v.y *= s;
        } else { // IN_RATIO
            float r = 1.f;
            if (y >= EXT && y < N-EXT && x >= EXT && x < N-EXT)
                r = g_ImgExp[y*N + x] / (g_ImgEst[y*N + x] + g_medScale);
            v = make_float2(r, 0.f);
        }
        rows[rr*STRIDE + x] = v;
    }
    __syncthreads();

    // one warp per row
    int w = tid >> 5, lane = tid & 31;
    float2* R = rows + w*STRIDE;
    if (!inverse){
        for (int s = LOGN-1; s >= 0; s--){
            int half = 1 << s;
            for (int b = lane; b < N/2; b += 32){
                int j  = b & (half-1);
                int i0 = ((b >> s) << (s+1)) | j;
                float2 a = R[i0], c = R[i0+half];
                float2 d = make_float2(a.x-c.x, a.y-c.y);
                R[i0]      = make_float2(a.x+c.x, a.y+c.y);
                R[i0+half] = cmul(d, tw[j << (LOGN-1-s)]);
            }
            __syncwarp();
        }
    } else {
        for (int s = 0; s < LOGN; s++){
            int half = 1 << s;
            for (int b = lane; b < N/2; b += 32){
                int j  = b & (half-1);
                int i0 = ((b >> s) << (s+1)) | j;
                float2 wt = tw[j << (LOGN-1-s)]; wt.y = -wt.y;  // conj for inverse
                float2 a = R[i0];
                float2 t = cmul(R[i0+half], wt);
                R[i0]      = make_float2(a.x+t.x, a.y+t.y);
                R[i0+half] = make_float2(a.x-t.x, a.y-t.y);
            }
            __syncwarp();
        }
    }
    __syncthreads();

    // transposed store: 4 consecutive rows -> 32B contiguous segments (full sectors)
    for (int e = tid; e < ROWS*N; e += TPB){
        int rr = e & (ROWS-1);
        int i  = e >> 2;
        dst[poff + (size_t)i*N + (row0 + rr)] = rows[rr*STRIDE + i];
    }
}

// ---------------- post-FFT kernels ----------------
__global__ void k_accum(){
    int i = blockIdx.x*blockDim.x + threadIdx.x;
    if (i >= NN) return;
    float acc = 0.f;
    #pragma unroll
    for (int p = 0; p < PAIRS; p++){
        float2 v = g_W[(size_t)p*NN + i];
        acc += fmaxf(v.x, 0.f) + fmaxf(v.y, 0.f);
    }
    g_ImgEst[i] = acc;
}

__global__ void k_hist_top(){
    for (int i = blockIdx.x*blockDim.x + threadIdx.x; i < NN; i += gridDim.x*blockDim.x){
        unsigned u = __float_as_uint(g_ImgEst[i]);   // values >= 0: bit-order == value-order
        atomicAdd(&g_hist[u >> 16], 1u);
    }
}

__global__ void k_scan_top(){
    __shared__ unsigned part[1024];
    int t = threadIdx.x;
    unsigned local = 0;
    for (int i = 0; i < 64; i++) local += g_hist[(t<<6) + i];
    part[t] = local; __syncthreads();
    for (int off = 1; off < 1024; off <<= 1){
        unsigned v = (t >= off) ? part[t-off] : 0u;
        __syncthreads();
        part[t] += v;
        __syncthreads();
    }
    unsigned cum = part[t] - local;
    for (int i = 0; i < 64; i++){
        unsigned c = g_hist[(t<<6) + i];
        if (KSEL0 >= cum && KSEL0 < cum + c){ g_sel[0] = (t<<6)+i; g_sel[1] = KSEL0 - cum; }
        if (KSEL1 >= cum && KSEL1 < cum + c){ g_sel[2] = (t<<6)+i; g_sel[3] = KSEL1 - cum; }
        cum += c;
    }
}

__global__ void k_hist_low(int which){
    unsigned bin = g_sel[which*2];
    for (int i = blockIdx.x*blockDim.x + threadIdx.x; i < NN; i += gridDim.x*blockDim.x){
        unsigned u = __float_as_uint(g_ImgEst[i]);
        if ((u >> 16) == bin) atomicAdd(&g_hist[u & 0xFFFFu], 1u);
    }
}

__global__ void k_scan_low(int which){
    __shared__ unsigned part[1024];
    int t = threadIdx.x;
    unsigned local = 0;
    for (int i = 0; i < 64; i++) local += g_hist[(t<<6) + i];
    part[t] = local; __syncthreads();
    for (int off = 1; off < 1024; off <<= 1){
        unsigned v = (t >= off) ? part[t-off] : 0u;
        __syncthreads();
        part[t] += v;
        __syncthreads();
    }
    unsigned cum = part[t] - local;
    unsigned k   = g_sel[which*2 + 1];
    unsigned bin = g_sel[which*2];
    for (int i = 0; i < 64; i++){
        unsigned c = g_hist[(t<<6) + i];
        if (k >= cum && k < cum + c) g_val[which] = (bin << 16) | ((t<<6) + i);
        cum += c;
    }
}

__global__ void k_med_final(){
    float v0 = __uint_as_float(g_val[0]);
    float v1 = __uint_as_float(g_val[1]);
    g_medScale = 0.5f*(v0 + v1) / SNRV;
}

__global__ void k_update(float* __restrict__ obj){
    int i = blockIdx.x*blockDim.x + threadIdx.x;
    if (i >= ROI2*ROI2) return;
    int r = i >> 9, c = i & 511;
    float b = g_W[(size_t)(LO + r)*N + (LO + c)].x;
    b = fmaxf(b, 0.f);
    #pragma unroll
    for (int z = 0; z < NZ; z++)
        obj[(size_t)z*ROI2*ROI2 + i] *= b;
}

// ---------------- launch sequence ----------------
extern "C" void kernel_launch(void* const* d_in, const int* in_sizes, int n_in,
                              void* d_out, int out_size)
{
    const float* imstack   = (const float*)d_in[0];
    const float* init_vol  = (const float*)d_in[1];
    const float* conv_real = (const float*)d_in[2];
    const float* conv_imag = (const float*)d_in[3];
    float* obj = (float*)d_out;

    void *wp, *w2p, *histPtr;
    cudaGetSymbolAddress(&wp,  g_W);
    cudaGetSymbolAddress(&w2p, g_W2);
    cudaGetSymbolAddress(&histPtr, g_hist);
    float2* W  = (float2*)wp;
    float2* W2 = (float2*)w2p;

    cudaMemcpyAsync(obj, init_vol, (size_t)NZ*ROI2*ROI2*sizeof(float),
                    cudaMemcpyDeviceToDevice, 0);
    k_zero_scalars<<<1,1>>>();
    k_tw<<<2,256>>>();
    k_imgexp<<<NN/256,256>>>(imstack);
    k_ksum<<<512,256>>>(conv_real);
    k_scale_final<<<1,1>>>();
    k_kh<<<NN/256,256>>>(conv_real, conv_imag);

    dim3 g12(N/ROWS, PAIRS), g1(N/ROWS, 1);

    for (int it = 0; it < ITN; it++){
        // forward projection: pack z-pairs, 2D FFT, *Kh/(N^2 Ksum), inverse 2D FFT
        k_fft<<<g12, TPB>>>(nullptr, W2, IN_PAIRS,   0, obj);
        k_fft<<<g12, TPB>>>(W2,      W,  IN_PLANE,   0, nullptr);
        k_fft<<<g12, TPB>>>(W,       W2, IN_SPECMUL, 1, nullptr);
        k_fft<<<g12, TPB>>>(W2,      W,  IN_PLANE,   1, nullptr);
        k_accum<<<NN/256,256>>>();

        // exact median of ImgEst (two middle order stats) via 2-level radix select
        cudaMemsetAsync(histPtr, 0, 65536*sizeof(unsigned), 0);
        k_hist_top<<<512,256>>>();
        k_scan_top<<<1,1024>>>();
        cudaMemsetAsync(histPtr, 0, 65536*sizeof(unsigned), 0);
        k_hist_low<<<512,256>>>(0);
        k_scan_low<<<1,1024>>>(0);
        cudaMemsetAsync(histPtr, 0, 65536*sizeof(unsigned), 0);
        k_hist_low<<<512,256>>>(1);
        k_scan_low<<<1,1024>>>(1);
        k_med_final<<<1,1>>>();

        // back projection: Ratio -> 2D FFT -> *conj(Kh)/(N^2 Ksum) -> inverse
        k_fft<<<g1, TPB>>>(nullptr, W2, IN_RATIO,        0, nullptr);
        k_fft<<<g1, TPB>>>(W2,      W,  IN_PLANE,        0, nullptr);
        k_fft<<<g1, TPB>>>(W,       W2, IN_SPECMUL_CONJ, 1, nullptr);
        k_fft<<<g1, TPB>>>(W2,      W,  IN_PLANE,        1, nullptr);

        k_update<<<(ROI2*ROI2)/256,256>>>(obj);
    }
}

// round 6
// speedup vs baseline: 1.2091x; 1.2091x over previous
#include <cuda_runtime.h>
#include <cstdint>

#define N        1024
#define LOGN     10
#define NN       (1<<20)
#define NZ       24
#define PAIRS    12
#define ROI2     512
#define LO       256
#define HIX      768
#define EXT      64
#define INNER    896
#define SNRV     200.0f
#define BKG      110.0f
#define ITN      2
#define KSEL0    524287u
#define KSEL1    524288u

#define ROWS     4
#define STRIDE   1032          /* float2 row pitch in shared (pad: 2-way max on final read) */
#define TPB      128

// ---------------- static device scratch (no runtime allocation allowed) ----------------
__device__ float2   g_W [(size_t)PAIRS * NN];   // 96 MB ping
__device__ float2   g_W2[(size_t)PAIRS * NN];   // 96 MB pong
__device__ float2   g_Kh[NN];                   // Hermitian kernel spectrum, natural layout
__device__ float    g_ImgExp[NN];
__device__ float    g_ImgEst[NN];
__device__ float2   g_tw[N/2];                  // W_1024^k, k=0..511 (double-precision gen)
__device__ double   g_ksum;
__device__ float    g_scale;                    // 1/(N^2 * Ksum)
__device__ unsigned g_hist[65536];
__device__ unsigned g_sel[4];                   // bin0, rem0, bin1, rem1
__device__ unsigned g_val[2];
__device__ float    g_medScale;                 // median / SNR

// W_32^k = TWC[k] - i*TWS[k] (forward), k = 0..15
__device__ __constant__ float TWC[16] = {
    1.0f, 0.980785280403230f, 0.923879532511287f, 0.831469612302545f,
    0.707106781186548f, 0.555570233019602f, 0.382683432365090f, 0.195090322016128f,
    0.0f, -0.195090322016128f, -0.382683432365090f, -0.555570233019602f,
    -0.707106781186548f, -0.831469612302545f, -0.923879532511287f, -0.980785280403230f};
__device__ __constant__ float TWS[16] = {
    0.0f, 0.195090322016128f, 0.382683432365090f, 0.555570233019602f,
    0.707106781186548f, 0.831469612302545f, 0.923879532511287f, 0.980785280403230f,
    1.0f, 0.980785280403230f, 0.923879532511287f, 0.831469612302545f,
    0.707106781186548f, 0.555570233019602f, 0.382683432365090f, 0.195090322016128f};

__device__ __forceinline__ float2 cmul(float2 a, float2 b){
    return make_float2(a.x*b.x - a.y*b.y, a.x*b.y + a.y*b.x);
}

// fully-unrolled 32-point FFT in registers, natural in -> natural out.
// INV=0: e^{-2pi i}, INV=1: e^{+2pi i} (unnormalized inverse)
template<int INV>
__device__ __forceinline__ void fft32(float2 r[32]){
    // bit-reverse (5-bit) permutation — compile-time swaps
    #define SW(a,b) { float2 t_ = r[a]; r[a] = r[b]; r[b] = t_; }
    SW(1,16) SW(2,8) SW(3,24) SW(5,20) SW(6,12) SW(7,28)
    SW(9,18) SW(11,26) SW(13,22) SW(15,30) SW(19,25) SW(23,29)
    #undef SW
    #pragma unroll
    for (int s = 1; s <= 5; s++){
        const int m = 1 << s, h = m >> 1;
        #pragma unroll
        for (int k = 0; k < 32; k += m){
            #pragma unroll
            for (int j = 0; j < h; j++){
                const int ti = j << (5 - s);
                float2 b = r[k+j+h], t;
                if (ti == 0)       t = b;
                else if (ti == 8)  t = INV ? make_float2(-b.y, b.x) : make_float2(b.y, -b.x);
                else {
                    float2 w = make_float2(TWC[ti], INV ? TWS[ti] : -TWS[ti]);
                    t = cmul(b, w);
                }
                float2 a = r[k+j];
                r[k+j]   = make_float2(a.x + t.x, a.y + t.y);
                r[k+j+h] = make_float2(a.x - t.x, a.y - t.y);
            }
        }
    }
}

// ---------------- setup kernels ----------------
__global__ void k_zero_scalars(){ g_ksum = 0.0; }

__global__ void k_tw(){
    int k = blockIdx.x*blockDim.x + threadIdx.x;
    if (k < N/2){
        double a = -6.283185307179586 * (double)k / (double)N;
        g_tw[k] = make_float2((float)cos(a), (float)sin(a));
    }
}

__global__ void k_imgexp(const float* __restrict__ img){
    int i = blockIdx.x*blockDim.x + threadIdx.x;
    if (i >= NN) return;
    int y = i >> LOGN, x = i & (N-1);
    float v = 0.f;
    if (y >= EXT && y < N-EXT && x >= EXT && x < N-EXT){
        float t = img[(y-EXT)*INNER + (x-EXT)] - BKG;
        v = t > 0.f ? t : 0.f;
    }
    g_ImgExp[i] = v;
}

__global__ void k_ksum(const float* __restrict__ cr){
    __shared__ float s[256];
    float acc = 0.f;
    for (int i = blockIdx.x*blockDim.x + threadIdx.x; i < NN; i += gridDim.x*blockDim.x)
        acc += cr[i];
    s[threadIdx.x] = acc; __syncthreads();
    for (int o = 128; o > 0; o >>= 1){
        if (threadIdx.x < o) s[threadIdx.x] += s[threadIdx.x+o];
        __syncthreads();
    }
    if (threadIdx.x == 0) atomicAdd(&g_ksum, (double)s[0]);
}

__global__ void k_scale_final(){
    g_scale = (float)(1.0 / (1048576.0 * g_ksum));
}

// Kh(f) = (K(f)+conj(K(-f)))/2, natural layout
__global__ void k_kh(const float* __restrict__ cr, const float* __restrict__ ci){
    int i = blockIdx.x*blockDim.x + threadIdx.x;
    if (i >= NN) return;
    int y = i >> LOGN, x = i & (N-1);
    int ny = (N - y) & (N-1), nx = (N - x) & (N-1);
    float kr = cr[i], ki = ci[i];
    float mr = cr[ny*N + nx], mi = ci[ny*N + nx];
    g_Kh[i] = make_float2(0.5f*(kr + mr), 0.5f*(ki - mi));
}

// ---------------- fused 1D-FFT (four-step, register-resident) + transpose pass ----------
enum { IN_PLANE=0, IN_PAIRS=1, IN_PLANE_Z=2, IN_SPECMUL=3, IN_SPECMUL_CONJ=4, IN_RATIO=5 };

template<int INV>
__global__ void __launch_bounds__(TPB)
k_fft(const float2* __restrict__ src, float2* __restrict__ dst,
      int mode, const float* __restrict__ obj)
{
    __shared__ float2 sh[ROWS*STRIDE];

    int tid  = threadIdx.x;
    int p    = blockIdx.y;
    int row0 = (mode == IN_PAIRS ? LO : 0) + blockIdx.x * ROWS;
    size_t poff = (size_t)p * NN;

    // coalesced load of ROWS rows, with fused input construction
    for (int e = tid; e < ROWS*N; e += TPB){
        int rr = e >> LOGN;
        int x  = e & (N-1);
        int y  = row0 + rr;
        float2 v;
        if (mode == IN_PLANE){
            v = src[poff + (size_t)y*N + x];
        } else if (mode == IN_PLANE_Z){
            v = make_float2(0.f, 0.f);
            if (x >= LO && x < HIX) v = src[poff + (size_t)y*N + x];
        } else if (mode == IN_PAIRS){
            v = make_float2(0.f, 0.f);
            if (x >= LO && x < HIX){
                int r = (y-LO)*ROI2 + (x-LO);
                v.x = obj[(size_t)(2*p  )*ROI2*ROI2 + r];
                v.y = obj[(size_t)(2*p+1)*ROI2*ROI2 + r];
            }
        } else if (mode == IN_SPECMUL || mode == IN_SPECMUL_CONJ){
            float2 a = src[poff + (size_t)y*N + x];
            float2 k = g_Kh[(size_t)y*N + x];
            if (mode == IN_SPECMUL_CONJ) k.y = -k.y;
            float s = g_scale;
            v = cmul(a, k); v.x *= s; v.y *= s;
        } else { // IN_RATIO
            float r = 1.f;
            if (y >= EXT && y < N-EXT && x >= EXT && x < N-EXT)
                r = g_ImgExp[(size_t)y*N + x] / (g_ImgEst[(size_t)y*N + x] + g_medScale);
            v = make_float2(r, 0.f);
        }
        sh[rr*STRIDE + x] = v;
    }
    __syncthreads();

    // four-step 1024-pt FFT: one warp per row, all butterflies in registers
    int w = tid >> 5, lane = tid & 31;
    float2* R = sh + w*STRIDE;

    float2 r[32];
    #pragma unroll
    for (int j = 0; j < 32; j++) r[j] = R[lane + 32*j];   // n1 = lane, reg idx = n2

    fft32<INV>(r);                                        // over n2 -> k2

    // twiddle W_1024^{+/- lane*k2}, incremental
    {
        float2 w1 = g_tw[lane];
        if (INV) w1.y = -w1.y;
        float2 t = w1;
        #pragma unroll
        for (int k2 = 1; k2 < 32; k2++){
            r[k2] = cmul(r[k2], t);
            t = cmul(t, w1);
        }
    }

    __syncwarp();
    #pragma unroll
    for (int k2 = 0; k2 < 32; k2++) R[32*k2 + lane] = r[k2];   // store [k2][n1]
    __syncwarp();
    #pragma unroll
    for (int n1 = 0; n1 < 32; n1++) r[n1] = R[32*lane + n1];   // lane = k2, reg = n1
    fft32<INV>(r);                                             // over n1 -> k1
    __syncwarp();
    #pragma unroll
    for (int k1 = 0; k1 < 32; k1++) R[32*k1 + lane] = r[k1];   // X[32*k1 + k2], natural
    __syncthreads();

    // transposed store: 4 consecutive rows -> 32B contiguous sectors
    for (int e = tid; e < ROWS*N; e += TPB){
        int rr = e & (ROWS-1);
        int i  = e >> 2;
        dst[poff + (size_t)i*N + (row0 + rr)] = sh[rr*STRIDE + i];
    }
}

// ---------------- post-FFT kernels ----------------
__global__ void k_accum(){
    int i = blockIdx.x*blockDim.x + threadIdx.x;
    if (i >= NN) return;
    float acc = 0.f;
    #pragma unroll
    for (int p = 0; p < PAIRS; p++){
        float2 v = g_W[(size_t)p*NN + i];
        acc += fmaxf(v.x, 0.f) + fmaxf(v.y, 0.f);
    }
    g_ImgEst[i] = acc;
}

__global__ void k_hist_top(){
    for (int i = blockIdx.x*blockDim.x + threadIdx.x; i < NN; i += gridDim.x*blockDim.x){
        unsigned u = __float_as_uint(g_ImgEst[i]);   // values >= 0: bit-order == value-order
        atomicAdd(&g_hist[u >> 16], 1u);
    }
}

__global__ void k_scan_top(){
    __shared__ unsigned part[1024];
    int t = threadIdx.x;
    unsigned local = 0;
    for (int i = 0; i < 64; i++) local += g_hist[(t<<6) + i];
    part[t] = local; __syncthreads();
    for (int off = 1; off < 1024; off <<= 1){
        unsigned v = (t >= off) ? part[t-off] : 0u;
        __syncthreads();
        part[t] += v;
        __syncthreads();
    }
    unsigned cum = part[t] - local;
    for (int i = 0; i < 64; i++){
        unsigned c = g_hist[(t<<6) + i];
        if (KSEL0 >= cum && KSEL0 < cum + c){ g_sel[0] = (t<<6)+i; g_sel[1] = KSEL0 - cum; }
        if (KSEL1 >= cum && KSEL1 < cum + c){ g_sel[2] = (t<<6)+i; g_sel[3] = KSEL1 - cum; }
        cum += c;
    }
}

__global__ void k_hist_low(int which){
    unsigned bin = g_sel[which*2];
    for (int i = blockIdx.x*blockDim.x + threadIdx.x; i < NN; i += gridDim.x*blockDim.x){
        unsigned u = __float_as_uint(g_ImgEst[i]);
        if ((u >> 16) == bin) atomicAdd(&g_hist[u & 0xFFFFu], 1u);
    }
}

__global__ void k_scan_low(int which){
    __shared__ unsigned part[1024];
    int t = threadIdx.x;
    unsigned local = 0;
    for (int i = 0; i < 64; i++) local += g_hist[(t<<6) + i];
    part[t] = local; __syncthreads();
    for (int off = 1; off < 1024; off <<= 1){
        unsigned v = (t >= off) ? part[t-off] : 0u;
        __syncthreads();
        part[t] += v;
        __syncthreads();
    }
    unsigned cum = part[t] - local;
    unsigned k   = g_sel[which*2 + 1];
    unsigned bin = g_sel[which*2];
    for (int i = 0; i < 64; i++){
        unsigned c = g_hist[(t<<6) + i];
        if (k >= cum && k < cum + c) g_val[which] = (bin << 16) | ((t<<6) + i);
        cum += c;
    }
}

__global__ void k_med_final(){
    float v0 = __uint_as_float(g_val[0]);
    float v1 = __uint_as_float(g_val[1]);
    g_medScale = 0.5f*(v0 + v1) / SNRV;
}

__global__ void k_update(float* __restrict__ obj){
    int i = blockIdx.x*blockDim.x + threadIdx.x;
    if (i >= ROI2*ROI2) return;
    int r = i >> 9, c = i & 511;
    float b = g_W[(size_t)(LO + r)*N + (LO + c)].x;
    b = fmaxf(b, 0.f);
    #pragma unroll
    for (int z = 0; z < NZ; z++)
        obj[(size_t)z*ROI2*ROI2 + i] *= b;
}

// ---------------- launch sequence ----------------
extern "C" void kernel_launch(void* const* d_in, const int* in_sizes, int n_in,
                              void* d_out, int out_size)
{
    const float* imstack   = (const float*)d_in[0];
    const float* init_vol  = (const float*)d_in[1];
    const float* conv_real = (const float*)d_in[2];
    const float* conv_imag = (const float*)d_in[3];
    float* obj = (float*)d_out;

    void *wp, *w2p, *histPtr;
    cudaGetSymbolAddress(&wp,  g_W);
    cudaGetSymbolAddress(&w2p, g_W2);
    cudaGetSymbolAddress(&histPtr, g_hist);
    float2* W  = (float2*)wp;
    float2* W2 = (float2*)w2p;

    cudaMemcpyAsync(obj, init_vol, (size_t)NZ*ROI2*ROI2*sizeof(float),
                    cudaMemcpyDeviceToDevice, 0);
    k_zero_scalars<<<1,1>>>();
    k_tw<<<2,256>>>();
    k_imgexp<<<NN/256,256>>>(imstack);
    k_ksum<<<512,256>>>(conv_real);
    k_scale_final<<<1,1>>>();
    k_kh<<<NN/256,256>>>(conv_real, conv_imag);

    dim3 gPairs(ROI2/ROWS, PAIRS);   // forward pass 1: only ROI rows are nonzero
    dim3 g12(N/ROWS, PAIRS), g1(N/ROWS, 1);

    for (int it = 0; it < ITN; it++){
        // forward projection: pack z-pairs, 2D FFT, *Kh/(N^2 Ksum), inverse 2D FFT
        k_fft<0><<<gPairs, TPB>>>(nullptr, W2, IN_PAIRS,   obj);
        k_fft<0><<<g12,    TPB>>>(W2,      W,  IN_PLANE_Z, nullptr);
        k_fft<1><<<g12,    TPB>>>(W,       W2, IN_SPECMUL, nullptr);
        k_fft<1><<<g12,    TPB>>>(W2,      W,  IN_PLANE,   nullptr);
        k_accum<<<NN/256,256>>>();

        // exact median of ImgEst (two middle order stats) via 2-level radix select
        cudaMemsetAsync(histPtr, 0, 65536*sizeof(unsigned), 0);
        k_hist_top<<<512,256>>>();
        k_scan_top<<<1,1024>>>();
        cudaMemsetAsync(histPtr, 0, 65536*sizeof(unsigned), 0);
        k_hist_low<<<512,256>>>(0);
        k_scan_low<<<1,1024>>>(0);
        cudaMemsetAsync(histPtr, 0, 65536*sizeof(unsigned), 0);
        k_hist_low<<<512,256>>>(1);
        k_scan_low<<<1,1024>>>(1);
        k_med_final<<<1,1>>>();

        // back projection: Ratio -> 2D FFT -> *conj(Kh)/(N^2 Ksum) -> inverse
        k_fft<0><<<g1, TPB>>>(nullptr, W2, IN_RATIO,        nullptr);
        k_fft<0><<<g1, TPB>>>(W2,      W,  IN_PLANE,        nullptr);
        k_fft<1><<<g1, TPB>>>(W,       W2, IN_SPECMUL_CONJ, nullptr);
        k_fft<1><<<g1, TPB>>>(W2,      W,  IN_PLANE,        nullptr);

        k_update<<<(ROI2*ROI2)/256,256>>>(obj);
    }
}